// round 7
// baseline (speedup 1.0000x reference)
#include <cuda_runtime.h>

#define NB 8
#define NN 2048
#define NH 128
#define EPSF 1e-8f

// Scratch (static __device__ globals — no allocations allowed)
__device__ float g_inv[2][NB * NN];        // per-row 1/max(||h||, eps)
__device__ float g_M[2][NB][NH * NH];      // g_M[t][b][l*128+k] = sum_m inv_t[m]*h_t[m,l]*h_t[m,k]
__device__ float g_W2T[NH * NH];           // g_W2T[l*128+k] = w_m[k,l]^2

// ------------------------------------------------------------------
// prep: inverse norms (blocks 0..4095), W2^T (4096..4159), zero M (4160..4415)
// ------------------------------------------------------------------
__global__ __launch_bounds__(256) void prep_kernel(
    const float* __restrict__ h1, const float* __restrict__ h2,
    const float* __restrict__ wm)
{
    int blk = blockIdx.x;
    if (blk < 4096) {
        int warp = threadIdx.x >> 5, lane = threadIdx.x & 31;
        int row = blk * 8 + warp;              // 0..32767
        int t = row >> 14;                      // 0: h1, 1: h2
        int idx = row & 16383;
        const float* src = t ? h2 : h1;
        float4 v = ((const float4*)(src + (size_t)idx * NH))[lane];
        float ss = v.x * v.x + v.y * v.y + v.z * v.z + v.w * v.w;
        #pragma unroll
        for (int o = 16; o; o >>= 1) ss += __shfl_xor_sync(0xffffffffu, ss, o);
        if (lane == 0) g_inv[t][idx] = 1.0f / fmaxf(sqrtf(ss), EPSF);
    } else if (blk < 4160) {
        int i = (blk - 4096) * 256 + threadIdx.x;   // i = l*128 + k
        int l = i >> 7, k = i & 127;
        float w = wm[k * NH + l];
        g_W2T[i] = w * w;
    } else {
        int i = (blk - 4160) * 256 + threadIdx.x;   // 65536 float4 = 262144 floats
        ((float4*)g_M)[i] = make_float4(0.f, 0.f, 0.f, 0.f);
    }
}

// ------------------------------------------------------------------
// M build: split-K SYRK-like, chunk=128 rows, atomicAdd accumulate.
// grid = 2*8*16 = 256 blocks, 256 threads.
// ------------------------------------------------------------------
__global__ __launch_bounds__(256) void mbuild_kernel(
    const float* __restrict__ h1, const float* __restrict__ h2)
{
    __shared__ float hs[32 * NH];
    __shared__ float sinv[32];
    int c = blockIdx.x & 15;
    int b = (blockIdx.x >> 4) & 7;
    int t = blockIdx.x >> 7;
    const float* src = t ? h2 : h1;
    const float* invp = g_inv[t] + b * NN;
    int tid = threadIdx.x;
    int tx = tid & 15, ty = tid >> 4;
    int k0 = tx * 4, l0 = ty * 4;

    float acc[8][8];
    #pragma unroll
    for (int i = 0; i < 8; i++)
        #pragma unroll
        for (int j = 0; j < 8; j++) acc[i][j] = 0.f;

    int rowbase = c * 128;
    for (int sub = 0; sub < 4; sub++) {
        int rb = rowbase + sub * 32;
        __syncthreads();
        const float4* g = (const float4*)(src + ((size_t)b * NN + rb) * NH);
        float4* s4 = (float4*)hs;
        #pragma unroll
        for (int i = 0; i < 4; i++) s4[tid + 256 * i] = g[tid + 256 * i];
        if (tid < 32) sinv[tid] = invp[rb + tid];
        __syncthreads();

        #pragma unroll 4
        for (int m = 0; m < 32; m++) {
            float s = sinv[m];
            float4 la = *(const float4*)&hs[m * NH + l0];
            float4 lb = *(const float4*)&hs[m * NH + l0 + 64];
            float4 ka = *(const float4*)&hs[m * NH + k0];
            float4 kb = *(const float4*)&hs[m * NH + k0 + 64];
            float lv[8] = {la.x * s, la.y * s, la.z * s, la.w * s,
                           lb.x * s, lb.y * s, lb.z * s, lb.w * s};
            float kv[8] = {ka.x, ka.y, ka.z, ka.w, kb.x, kb.y, kb.z, kb.w};
            #pragma unroll
            for (int i = 0; i < 8; i++)
                #pragma unroll
                for (int j = 0; j < 8; j++) acc[i][j] += lv[i] * kv[j];
        }
    }

    float* Mp = g_M[t][b];
    #pragma unroll
    for (int i = 0; i < 8; i++) {
        int l = l0 + ((i < 4) ? i : 60 + i);
        #pragma unroll
        for (int j = 0; j < 8; j++) {
            int k = k0 + ((j < 4) ? j : 60 + j);
            atomicAdd(&Mp[l * NH + k], acc[i][j]);
        }
    }
}

// ------------------------------------------------------------------
// fused fm: per 32-row tile of (t, b):
//   phase 1: y = (x @ M_{1-t}) * inv_t[row]
//   build   : u = x*y, a = x*x, c = y*y  (smem)
//   phase 2: NUM = u@W2T, DXX = a@W2T, DYY = c@W2T  (shared B tile)
//   epilogue: out = NUM / (max(sqrt(DXX),eps)*max(sqrt(DYY),eps))
// grid = 2*8*64 = 1024 blocks, 256 threads, 208 KB dynamic smem.
// ------------------------------------------------------------------
__global__ __launch_bounds__(256, 1) void fm_kernel(
    const float* __restrict__ h1, const float* __restrict__ h2,
    float* __restrict__ out)
{
    extern __shared__ float smem[];
    float* Ms  = smem;              // 16384 floats
    float* Ws  = smem + 16384;      // 16384
    float* xs  = smem + 32768;      // 4096
    float* ys  = smem + 36864;      // 4096
    float* us  = smem + 40960;      // 4096
    float* as_ = smem + 45056;      // 4096
    float* cs  = smem + 49152;      // 4096  -> total 53248 floats = 212992 B

    int rt = blockIdx.x & 63;
    int b  = (blockIdx.x >> 6) & 7;
    int t  = blockIdx.x >> 9;
    const float* src = t ? h2 : h1;
    const float* Mg = g_M[1 - t][b];
    int tid = threadIdx.x;

    // fill smem: M tile, W2T tile, x rows
    {
        const float4* mg4 = (const float4*)Mg;
        const float4* wg4 = (const float4*)g_W2T;
        float4* ms4 = (float4*)Ms;
        float4* ws4 = (float4*)Ws;
        #pragma unroll
        for (int i = 0; i < 16; i++) {
            ms4[tid + 256 * i] = mg4[tid + 256 * i];
            ws4[tid + 256 * i] = wg4[tid + 256 * i];
        }
        const float4* xg = (const float4*)(src + ((size_t)b * NN + rt * 32) * NH);
        float4* xs4 = (float4*)xs;
        #pragma unroll
        for (int i = 0; i < 4; i++) xs4[tid + 256 * i] = xg[tid + 256 * i];
    }
    __syncthreads();

    int tx = tid & 31, ty = tid >> 5;
    int k0 = tx * 4;
    int r0 = ty * 4;

    // ---- phase 1: y = x @ M ----
    float a1[4][4];
    #pragma unroll
    for (int r = 0; r < 4; r++)
        #pragma unroll
        for (int j = 0; j < 4; j++) a1[r][j] = 0.f;

    #pragma unroll 4
    for (int l = 0; l < NH; l += 4) {
        float4 w0 = *(const float4*)&Ms[(l + 0) * NH + k0];
        float4 w1 = *(const float4*)&Ms[(l + 1) * NH + k0];
        float4 w2 = *(const float4*)&Ms[(l + 2) * NH + k0];
        float4 w3 = *(const float4*)&Ms[(l + 3) * NH + k0];
        #pragma unroll
        for (int r = 0; r < 4; r++) {
            float4 xv = *(const float4*)&xs[(r0 + r) * NH + l];
            a1[r][0] += xv.x * w0.x; a1[r][1] += xv.x * w0.y; a1[r][2] += xv.x * w0.z; a1[r][3] += xv.x * w0.w;
            a1[r][0] += xv.y * w1.x; a1[r][1] += xv.y * w1.y; a1[r][2] += xv.y * w1.z; a1[r][3] += xv.y * w1.w;
            a1[r][0] += xv.z * w2.x; a1[r][1] += xv.z * w2.y; a1[r][2] += xv.z * w2.z; a1[r][3] += xv.z * w2.w;
            a1[r][0] += xv.w * w3.x; a1[r][1] += xv.w * w3.y; a1[r][2] += xv.w * w3.z; a1[r][3] += xv.w * w3.w;
        }
    }
    const float* invp = g_inv[t] + b * NN + rt * 32;
    #pragma unroll
    for (int r = 0; r < 4; r++) {
        float s = invp[r0 + r];
        float4 v = make_float4(a1[r][0] * s, a1[r][1] * s, a1[r][2] * s, a1[r][3] * s);
        *(float4*)&ys[(r0 + r) * NH + k0] = v;
    }
    __syncthreads();

    // ---- build u, a, c tiles ----
    {
        const float4* x4 = (const float4*)xs;
        const float4* y4 = (const float4*)ys;
        float4* u4 = (float4*)us;
        float4* a4 = (float4*)as_;
        float4* c4 = (float4*)cs;
        #pragma unroll
        for (int i = 0; i < 4; i++) {
            int e = tid + 256 * i;
            float4 xv = x4[e], yv = y4[e];
            u4[e] = make_float4(xv.x * yv.x, xv.y * yv.y, xv.z * yv.z, xv.w * yv.w);
            a4[e] = make_float4(xv.x * xv.x, xv.y * xv.y, xv.z * xv.z, xv.w * xv.w);
            c4[e] = make_float4(yv.x * yv.x, yv.y * yv.y, yv.z * yv.z, yv.w * yv.w);
        }
    }
    __syncthreads();

    // ---- phase 2: three GEMMs sharing W2T ----
    float aN[4][4], aA[4][4], aC[4][4];
    #pragma unroll
    for (int r = 0; r < 4; r++)
        #pragma unroll
        for (int j = 0; j < 4; j++) { aN[r][j] = 0.f; aA[r][j] = 0.f; aC[r][j] = 0.f; }

    #pragma unroll 2
    for (int l = 0; l < NH; l += 4) {
        float4 w0 = *(const float4*)&Ws[(l + 0) * NH + k0];
        float4 w1 = *(const float4*)&Ws[(l + 1) * NH + k0];
        float4 w2 = *(const float4*)&Ws[(l + 2) * NH + k0];
        float4 w3 = *(const float4*)&Ws[(l + 3) * NH + k0];
        #pragma unroll
        for (int r = 0; r < 4; r++) {
            float4 uv = *(const float4*)&us[(r0 + r) * NH + l];
            float4 av = *(const float4*)&as_[(r0 + r) * NH + l];
            float4 cv = *(const float4*)&cs[(r0 + r) * NH + l];

            aN[r][0] += uv.x * w0.x; aN[r][1] += uv.x * w0.y; aN[r][2] += uv.x * w0.z; aN[r][3] += uv.x * w0.w;
            aN[r][0] += uv.y * w1.x; aN[r][1] += uv.y * w1.y; aN[r][2] += uv.y * w1.z; aN[r][3] += uv.y * w1.w;
            aN[r][0] += uv.z * w2.x; aN[r][1] += uv.z * w2.y; aN[r][2] += uv.z * w2.z; aN[r][3] += uv.z * w2.w;
            aN[r][0] += uv.w * w3.x; aN[r][1] += uv.w * w3.y; aN[r][2] += uv.w * w3.z; aN[r][3] += uv.w * w3.w;

            aA[r][0] += av.x * w0.x; aA[r][1] += av.x * w0.y; aA[r][2] += av.x * w0.z; aA[r][3] += av.x * w0.w;
            aA[r][0] += av.y * w1.x; aA[r][1] += av.y * w1.y; aA[r][2] += av.y * w1.z; aA[r][3] += av.y * w1.w;
            aA[r][0] += av.z * w2.x; aA[r][1] += av.z * w2.y; aA[r][2] += av.z * w2.z; aA[r][3] += av.z * w2.w;
            aA[r][0] += av.w * w3.x; aA[r][1] += av.w * w3.y; aA[r][2] += av.w * w3.z; aA[r][3] += av.w * w3.w;

            aC[r][0] += cv.x * w0.x; aC[r][1] += cv.x * w0.y; aC[r][2] += cv.x * w0.z; aC[r][3] += cv.x * w0.w;
            aC[r][0] += cv.y * w1.x; aC[r][1] += cv.y * w1.y; aC[r][2] += cv.y * w1.z; aC[r][3] += cv.y * w1.w;
            aC[r][0] += cv.z * w2.x; aC[r][1] += cv.z * w2.y; aC[r][2] += cv.z * w2.z; aC[r][3] += cv.z * w2.w;
            aC[r][0] += cv.w * w3.x; aC[r][1] += cv.w * w3.y; aC[r][2] += cv.w * w3.z; aC[r][3] += cv.w * w3.w;
        }
    }

    // ---- epilogue ----
    float* op = out + (((size_t)t * NB + b) * NN + rt * 32) * NH;
    #pragma unroll
    for (int r = 0; r < 4; r++) {
        float4 o;
        float d;
        d = fmaxf(sqrtf(aA[r][0]), EPSF) * fmaxf(sqrtf(aC[r][0]), EPSF); o.x = aN[r][0] / d;
        d = fmaxf(sqrtf(aA[r][1]), EPSF) * fmaxf(sqrtf(aC[r][1]), EPSF); o.y = aN[r][1] / d;
        d = fmaxf(sqrtf(aA[r][2]), EPSF) * fmaxf(sqrtf(aC[r][2]), EPSF); o.z = aN[r][2] / d;
        d = fmaxf(sqrtf(aA[r][3]), EPSF) * fmaxf(sqrtf(aC[r][3]), EPSF); o.w = aN[r][3] / d;
        *(float4*)&op[(r0 + r) * NH + k0] = o;
    }
}

extern "C" void kernel_launch(void* const* d_in, const int* in_sizes, int n_in,
                              void* d_out, int out_size) {
    const float* h1 = (const float*)d_in[0];
    const float* h2 = (const float*)d_in[1];
    const float* wm = (const float*)d_in[2];
    float* out = (float*)d_out;

    cudaFuncSetAttribute(fm_kernel, cudaFuncAttributeMaxDynamicSharedMemorySize, 212992);

    prep_kernel<<<4416, 256>>>(h1, h2, wm);
    mbuild_kernel<<<256, 256>>>(h1, h2);
    fm_kernel<<<1024, 256, 212992>>>(h1, h2, out);
}